// round 2
// baseline (speedup 1.0000x reference)
#include <cuda_runtime.h>
#include <math.h>

// ---------------------------------------------------------------------------
// TrigramAttention: y = OutProj( BandedAttn( QKV(x) ) )
//   B=8, T=4096, C=1024, H=16, d=64, WINDOW=3
// Round 1: correct fp32 baseline.
//   - 4x SGEMM (NT, bias): M=32768, N=1024, K=1024, 128x128x16 tiles, 8x8/thread
//   - banded attention kernel: warp per (row, head)
// ---------------------------------------------------------------------------

#define C_EMBD 1024
#define T_LEN  4096
#define MAX_ROWS (8 * 4096)

// scratch (allocation-free rule: __device__ globals)
__device__ float g_q[(size_t)MAX_ROWS * C_EMBD];
__device__ float g_k[(size_t)MAX_ROWS * C_EMBD];
__device__ float g_v[(size_t)MAX_ROWS * C_EMBD];
__device__ float g_y[(size_t)MAX_ROWS * C_EMBD];

// ---------------------------------------------------------------------------
// SGEMM (NT): C[m,n] = sum_k A[m,k] * B[n,k] + bias[n]
// A: [M,K] row-major, B: [N,K] row-major (torch Linear weight), both K-contig.
// Tiles: BM=128, BN=128, BK=16. 256 threads, each computes 8x8.
// M % 128 == 0, N % 128 == 0, K % 16 == 0 assumed (holds: 32768,1024,1024).
// ---------------------------------------------------------------------------
__global__ __launch_bounds__(256, 2)
void sgemm_nt_bias(const float* __restrict__ A,
                   const float* __restrict__ B,
                   const float* __restrict__ bias,
                   float* __restrict__ C,
                   int M, int N, int K)
{
    __shared__ float As[16][128];
    __shared__ float Bs[16][128];

    const int tid = threadIdx.x;
    const int tx  = tid & 15;   // n direction (8 cols each)
    const int ty  = tid >> 4;   // m direction (8 rows each)
    const int bm  = blockIdx.y * 128;
    const int bn  = blockIdx.x * 128;

    float acc[8][8];
#pragma unroll
    for (int i = 0; i < 8; i++)
#pragma unroll
        for (int j = 0; j < 8; j++) acc[i][j] = 0.0f;

    for (int k0 = 0; k0 < K; k0 += 16) {
        // Load A tile (128 x 16) as 512 float4; 2 per thread, coalesced.
#pragma unroll
        for (int i = 0; i < 2; i++) {
            int idx = tid + i * 256;       // 0..511
            int row = idx >> 2;            // 0..127
            int c4  = idx & 3;             // 0..3
            float4 a = *(const float4*)(A + (size_t)(bm + row) * K + k0 + c4 * 4);
            As[c4 * 4 + 0][row] = a.x;
            As[c4 * 4 + 1][row] = a.y;
            As[c4 * 4 + 2][row] = a.z;
            As[c4 * 4 + 3][row] = a.w;
        }
        // Load B tile (128 x 16) same way.
#pragma unroll
        for (int i = 0; i < 2; i++) {
            int idx = tid + i * 256;
            int row = idx >> 2;
            int c4  = idx & 3;
            float4 b = *(const float4*)(B + (size_t)(bn + row) * K + k0 + c4 * 4);
            Bs[c4 * 4 + 0][row] = b.x;
            Bs[c4 * 4 + 1][row] = b.y;
            Bs[c4 * 4 + 2][row] = b.z;
            Bs[c4 * 4 + 3][row] = b.w;
        }
        __syncthreads();

#pragma unroll
        for (int kk = 0; kk < 16; kk++) {
            float a[8], b[8];
#pragma unroll
            for (int m = 0; m < 8; m++) a[m] = As[kk][ty * 8 + m];
#pragma unroll
            for (int n = 0; n < 8; n++) b[n] = Bs[kk][tx * 8 + n];
#pragma unroll
            for (int m = 0; m < 8; m++)
#pragma unroll
                for (int n = 0; n < 8; n++)
                    acc[m][n] += a[m] * b[n];
        }
        __syncthreads();
    }

    // epilogue with bias, float4 stores
    float bv[8];
#pragma unroll
    for (int n = 0; n < 8; n++) bv[n] = bias[bn + tx * 8 + n];

#pragma unroll
    for (int m = 0; m < 8; m++) {
        int grow = bm + ty * 8 + m;
        float* cp = C + (size_t)grow * N + bn + tx * 8;
        float4 o0, o1;
        o0.x = acc[m][0] + bv[0]; o0.y = acc[m][1] + bv[1];
        o0.z = acc[m][2] + bv[2]; o0.w = acc[m][3] + bv[3];
        o1.x = acc[m][4] + bv[4]; o1.y = acc[m][5] + bv[5];
        o1.z = acc[m][6] + bv[6]; o1.w = acc[m][7] + bv[7];
        *(float4*)(cp)     = o0;
        *(float4*)(cp + 4) = o1;
    }
}

// ---------------------------------------------------------------------------
// Banded trigram attention.
// grid.x = B*T (one block per token row), 512 threads = 16 warps = 16 heads.
// Each warp: lane holds q[lane], q[lane+32] of its head's d=64 slice.
// s_j = (q . k[t-j]) * 1/sqrt(64)  for j=0..2 (valid if t>=j), softmax over 3,
// y = sum_j a_j * v[t-j].
// ---------------------------------------------------------------------------
__global__ __launch_bounds__(512)
void trigram_attn(const float* __restrict__ q,
                  const float* __restrict__ k,
                  const float* __restrict__ v,
                  float* __restrict__ y)
{
    const int row  = blockIdx.x;            // b*T + t
    const int t    = row & (T_LEN - 1);     // T = 4096 (power of 2)
    const int head = threadIdx.x >> 5;
    const int lane = threadIdx.x & 31;

    const size_t base = (size_t)row * C_EMBD + head * 64;
    const float q0 = q[base + lane];
    const float q1 = q[base + 32 + lane];

    float s[3];
#pragma unroll
    for (int j = 0; j < 3; j++) {
        float p = 0.0f;
        if (t >= j) {
            const size_t kb = base - (size_t)j * C_EMBD;
            p = q0 * k[kb + lane] + q1 * k[kb + 32 + lane];
        }
#pragma unroll
        for (int off = 16; off > 0; off >>= 1)
            p += __shfl_xor_sync(0xFFFFFFFFu, p, off);
        s[j] = p * 0.125f;  // 1/sqrt(64)
    }

    // softmax over the valid window
    float m = s[0];
    if (t >= 1 && s[1] > m) m = s[1];
    if (t >= 2 && s[2] > m) m = s[2];
    float e0 = expf(s[0] - m);
    float e1 = (t >= 1) ? expf(s[1] - m) : 0.0f;
    float e2 = (t >= 2) ? expf(s[2] - m) : 0.0f;
    const float inv = 1.0f / (e0 + e1 + e2);
    const float a0 = e0 * inv, a1 = e1 * inv, a2 = e2 * inv;

    float y0 = a0 * v[base + lane];
    float y1 = a0 * v[base + 32 + lane];
    if (t >= 1) {
        y0 += a1 * v[base - C_EMBD + lane];
        y1 += a1 * v[base - C_EMBD + 32 + lane];
    }
    if (t >= 2) {
        y0 += a2 * v[base - 2 * (size_t)C_EMBD + lane];
        y1 += a2 * v[base - 2 * (size_t)C_EMBD + 32 + lane];
    }
    y[base + lane]      = y0;
    y[base + 32 + lane] = y1;
}

// ---------------------------------------------------------------------------
extern "C" void kernel_launch(void* const* d_in, const int* in_sizes, int n_in,
                              void* d_out, int out_size)
{
    const float* x  = (const float*)d_in[0];
    const float* Wq = (const float*)d_in[1];
    const float* bq = (const float*)d_in[2];
    const float* Wk = (const float*)d_in[3];
    const float* bk = (const float*)d_in[4];
    const float* Wv = (const float*)d_in[5];
    const float* bv = (const float*)d_in[6];
    const float* Wo = (const float*)d_in[7];
    const float* bo = (const float*)d_in[8];
    float* out = (float*)d_out;

    const int rows = in_sizes[0] / C_EMBD;   // B*T = 32768

    float *q, *k, *v, *y;
    cudaGetSymbolAddress((void**)&q, g_q);
    cudaGetSymbolAddress((void**)&k, g_k);
    cudaGetSymbolAddress((void**)&v, g_v);
    cudaGetSymbolAddress((void**)&y, g_y);

    dim3 gblk(256);
    dim3 ggrid(C_EMBD / 128, rows / 128);

    sgemm_nt_bias<<<ggrid, gblk>>>(x, Wq, bq, q, rows, C_EMBD, C_EMBD);
    sgemm_nt_bias<<<ggrid, gblk>>>(x, Wk, bk, k, rows, C_EMBD, C_EMBD);
    sgemm_nt_bias<<<ggrid, gblk>>>(x, Wv, bv, v, rows, C_EMBD, C_EMBD);

    trigram_attn<<<rows, 512>>>(q, k, v, y);

    sgemm_nt_bias<<<ggrid, gblk>>>(y, Wo, bo, out, rows, C_EMBD, C_EMBD);
}

// round 5
// speedup vs baseline: 2.6370x; 2.6370x over previous
#include <cuda_runtime.h>
#include <cuda_bf16.h>
#include <math.h>
#include <stdint.h>

// ---------------------------------------------------------------------------
// TrigramAttention on GB300 (sm_103a), Round 4:
//   tcgen05 rejected (harness compiles PTX at compute_103, no 'a' features).
//   => Ampere-style mma.sync.m16n8k16.bf16 register GEMM, 3-term split:
//      C = Ah*Bh^T + Ah*Bl^T + Al*Bh^T   (fp32 accum, err ~1e-5)
//   B=8, T=4096, C=1024, H=16, d=64, WINDOW=3
// ---------------------------------------------------------------------------

#define C_EMBD   1024
#define T_LEN    4096
#define MAX_ROWS (8 * 4096)

#define BK       64
#define NCHUNK   16                    // K=1024 / 64
#define TILE_B   16384                 // 128 rows x 128 bytes
#define STAGE_B  (4 * TILE_B)          // Ah, Al, Bh, Bl
#define GEMM_SMEM (2 * STAGE_B)        // 2-stage pipeline: 131072 B

// ---------------- scratch (__device__ globals: allocation-free rule) --------
__device__ __nv_bfloat16 g_xh[(size_t)MAX_ROWS * C_EMBD];
__device__ __nv_bfloat16 g_xl[(size_t)MAX_ROWS * C_EMBD];
__device__ __nv_bfloat16 g_yh[(size_t)MAX_ROWS * C_EMBD];
__device__ __nv_bfloat16 g_yl[(size_t)MAX_ROWS * C_EMBD];
__device__ __nv_bfloat16 g_wh[4][(size_t)C_EMBD * C_EMBD];
__device__ __nv_bfloat16 g_wl[4][(size_t)C_EMBD * C_EMBD];
__device__ float g_q[(size_t)MAX_ROWS * C_EMBD];
__device__ float g_k[(size_t)MAX_ROWS * C_EMBD];
__device__ float g_v[(size_t)MAX_ROWS * C_EMBD];

// ---------------- helpers ---------------------------------------------------
__device__ __forceinline__ uint32_t smem_u32(const void* p) {
    uint32_t a;
    asm("{ .reg .u64 t; cvta.to.shared.u64 t, %1; cvt.u32.u64 %0, t; }"
        : "=r"(a) : "l"(p));
    return a;
}
__device__ __forceinline__ void cp16(uint32_t dst, const void* src) {
    asm volatile("cp.async.cg.shared.global [%0], [%1], 16;"
                 :: "r"(dst), "l"(src) : "memory");
}
__device__ __forceinline__ uint32_t swz128(uint32_t off) {
    return off ^ ((off >> 3) & 0x70);
}
__device__ __forceinline__ void ldsm4(uint32_t* r, uint32_t addr) {
    asm volatile("ldmatrix.sync.aligned.m8n8.x4.shared.b16 {%0,%1,%2,%3}, [%4];"
                 : "=r"(r[0]), "=r"(r[1]), "=r"(r[2]), "=r"(r[3]) : "r"(addr));
}
__device__ __forceinline__ void mma16816(float* d, const uint32_t* a,
                                         uint32_t b0, uint32_t b1) {
    asm volatile(
        "mma.sync.aligned.m16n8k16.row.col.f32.bf16.bf16.f32 "
        "{%0,%1,%2,%3}, {%4,%5,%6,%7}, {%8,%9}, {%0,%1,%2,%3};"
        : "+f"(d[0]), "+f"(d[1]), "+f"(d[2]), "+f"(d[3])
        : "r"(a[0]), "r"(a[1]), "r"(a[2]), "r"(a[3]), "r"(b0), "r"(b1));
}
// ldmatrix source address inside a 128x(64 bf16) SW128-swizzled tile.
// lanes 0-15: rows rowBase+(lane&15) at col kk*16; lanes 16-31: same rows, col+8.
__device__ __forceinline__ uint32_t ldsm_addr(uint32_t tile, int rowBase,
                                              int kk, int lane) {
    int row   = rowBase + (lane & 15);
    int chunk = kk * 2 + (lane >> 4);          // 16B chunk index (col/8)
    return tile + (uint32_t)(row * 128 + ((chunk ^ (row & 7)) << 4));
}

// ---------------------------------------------------------------------------
// GEMM: C[m,n] = sum_k Ah[m,k]*Bh[n,k] + Ah*Bl + Al*Bh  + bias[n]
// A:[M,1024] bf16 row-major (hi/lo), B:[1024,1024] bf16 row-major (hi/lo).
// CTA tile 128x128, BK=64, 8 warps as 2(m)x4(n), warp tile 64x32.
// ---------------------------------------------------------------------------
__global__ __launch_bounds__(256, 1)
void gemm_bf16x3(const __nv_bfloat16* __restrict__ Ah,
                 const __nv_bfloat16* __restrict__ Al,
                 const __nv_bfloat16* __restrict__ Bh,
                 const __nv_bfloat16* __restrict__ Bl,
                 const float* __restrict__ bias,
                 float* __restrict__ Cout)
{
    extern __shared__ char smem[];
    const uint32_t sb = smem_u32(smem);
    const int tid  = threadIdx.x;
    const int wid  = tid >> 5;
    const int lane = tid & 31;
    const int wm   = wid & 1;          // 0..1  (64-row slice)
    const int wn   = wid >> 1;         // 0..3  (32-col slice)
    const int bn   = blockIdx.x * 128;
    const int bm   = blockIdx.y * 128;

    const char* pAh = (const char*)Ah + (size_t)bm * 2048;
    const char* pAl = (const char*)Al + (size_t)bm * 2048;
    const char* pBh = (const char*)Bh + (size_t)bn * 2048;
    const char* pBl = (const char*)Bl + (size_t)bn * 2048;

    float acc[4][4][4];
#pragma unroll
    for (int mt = 0; mt < 4; mt++)
#pragma unroll
        for (int nt = 0; nt < 4; nt++)
#pragma unroll
            for (int r = 0; r < 4; r++) acc[mt][nt][r] = 0.0f;

    // ---- stage loader: 64KB (4 tiles) per chunk ----
    auto load_stage = [&](int chunk, int s) {
        const uint32_t st = sb + s * STAGE_B;
        const size_t kb = (size_t)chunk * 128;     // 64 bf16 along K
#pragma unroll
        for (int u = 0; u < 4; ++u) {
            const int v   = tid + 256 * u;          // 0..1023
            const int row = v >> 3;
            const int c16 = v & 7;
            const uint32_t so = swz128((uint32_t)(row * 128 + c16 * 16));
            const size_t go   = (size_t)row * 2048 + kb + c16 * 16;
            cp16(st + so,              pAh + go);
            cp16(st + TILE_B + so,     pAl + go);
            cp16(st + 2 * TILE_B + so, pBh + go);
            cp16(st + 3 * TILE_B + so, pBl + go);
        }
        asm volatile("cp.async.commit_group;" ::: "memory");
    };

    load_stage(0, 0);

    for (int i = 0; i < NCHUNK; ++i) {
        if (i + 1 < NCHUNK) {
            load_stage(i + 1, (i + 1) & 1);
            asm volatile("cp.async.wait_group 1;" ::: "memory");
        } else {
            asm volatile("cp.async.wait_group 0;" ::: "memory");
        }
        __syncthreads();

        const uint32_t st  = sb + (i & 1) * STAGE_B;
        const uint32_t tAh = st;
        const uint32_t tAl = st + TILE_B;
        const uint32_t tBh = st + 2 * TILE_B;
        const uint32_t tBl = st + 3 * TILE_B;

#pragma unroll
        for (int kk = 0; kk < 4; ++kk) {
            uint32_t ah[4][4], al[4][4], bh[2][4], bl[2][4];
#pragma unroll
            for (int mt = 0; mt < 4; mt++)
                ldsm4(ah[mt], ldsm_addr(tAh, wm * 64 + mt * 16, kk, lane));
#pragma unroll
            for (int p = 0; p < 2; p++)
                ldsm4(bh[p], ldsm_addr(tBh, wn * 32 + p * 16, kk, lane));
#pragma unroll
            for (int mt = 0; mt < 4; mt++)
#pragma unroll
                for (int nt = 0; nt < 4; nt++)
                    mma16816(acc[mt][nt], ah[mt],
                             bh[nt >> 1][nt & 1], bh[nt >> 1][(nt & 1) + 2]);
#pragma unroll
            for (int p = 0; p < 2; p++)
                ldsm4(bl[p], ldsm_addr(tBl, wn * 32 + p * 16, kk, lane));
#pragma unroll
            for (int mt = 0; mt < 4; mt++)
#pragma unroll
                for (int nt = 0; nt < 4; nt++)
                    mma16816(acc[mt][nt], ah[mt],
                             bl[nt >> 1][nt & 1], bl[nt >> 1][(nt & 1) + 2]);
#pragma unroll
            for (int mt = 0; mt < 4; mt++)
                ldsm4(al[mt], ldsm_addr(tAl, wm * 64 + mt * 16, kk, lane));
#pragma unroll
            for (int mt = 0; mt < 4; mt++)
#pragma unroll
                for (int nt = 0; nt < 4; nt++)
                    mma16816(acc[mt][nt], al[mt],
                             bh[nt >> 1][nt & 1], bh[nt >> 1][(nt & 1) + 2]);
        }
        __syncthreads();
    }

    // ---- epilogue: fragment layout (g=lane>>2 row, t=lane&3 col pair) ----
    const int g = lane >> 2;
    const int t = lane & 3;
#pragma unroll
    for (int nt = 0; nt < 4; nt++) {
        const int col = bn + wn * 32 + nt * 8 + 2 * t;
        const float b0 = bias[col], b1 = bias[col + 1];
#pragma unroll
        for (int mt = 0; mt < 4; mt++) {
            const int row0 = bm + wm * 64 + mt * 16 + g;
            float2 v0 = {acc[mt][nt][0] + b0, acc[mt][nt][1] + b1};
            float2 v1 = {acc[mt][nt][2] + b0, acc[mt][nt][3] + b1};
            *(float2*)(Cout + (size_t)row0 * C_EMBD + col)       = v0;
            *(float2*)(Cout + (size_t)(row0 + 8) * C_EMBD + col) = v1;
        }
    }
}

// ---------------------------------------------------------------------------
// split fp32 -> bf16 hi/lo
// ---------------------------------------------------------------------------
__global__ __launch_bounds__(256)
void split_bf16(const float* __restrict__ in, __nv_bfloat16* __restrict__ hi,
                __nv_bfloat16* __restrict__ lo, int n4)
{
    int i = blockIdx.x * 256 + threadIdx.x;
    if (i >= n4) return;
    float4 x = ((const float4*)in)[i];
    __nv_bfloat16 h[4], l[4];
    float v[4] = {x.x, x.y, x.z, x.w};
#pragma unroll
    for (int c = 0; c < 4; ++c) {
        h[c] = __float2bfloat16(v[c]);
        l[c] = __float2bfloat16(v[c] - __bfloat162float(h[c]));
    }
    ((ushort4*)hi)[i] = *(ushort4*)h;
    ((ushort4*)lo)[i] = *(ushort4*)l;
}

// ---------------------------------------------------------------------------
// Banded trigram attention; emits y as bf16 hi/lo for the output projection.
// ---------------------------------------------------------------------------
__global__ __launch_bounds__(512)
void trigram_attn(const float* __restrict__ q, const float* __restrict__ k,
                  const float* __restrict__ v,
                  __nv_bfloat16* __restrict__ yh, __nv_bfloat16* __restrict__ yl)
{
    const int row  = blockIdx.x;
    const int t    = row & (T_LEN - 1);
    const int head = threadIdx.x >> 5;
    const int lane = threadIdx.x & 31;
    const size_t base = (size_t)row * C_EMBD + head * 64;

    const float q0 = q[base + lane];
    const float q1 = q[base + 32 + lane];

    float s[3];
#pragma unroll
    for (int j = 0; j < 3; j++) {
        float p = 0.0f;
        if (t >= j) {
            const size_t kb = base - (size_t)j * C_EMBD;
            p = q0 * k[kb + lane] + q1 * k[kb + 32 + lane];
        }
#pragma unroll
        for (int off = 16; off > 0; off >>= 1)
            p += __shfl_xor_sync(0xFFFFFFFFu, p, off);
        s[j] = p * 0.125f;
    }
    float m = s[0];
    if (t >= 1 && s[1] > m) m = s[1];
    if (t >= 2 && s[2] > m) m = s[2];
    float e0 = expf(s[0] - m);
    float e1 = (t >= 1) ? expf(s[1] - m) : 0.0f;
    float e2 = (t >= 2) ? expf(s[2] - m) : 0.0f;
    const float inv = 1.0f / (e0 + e1 + e2);
    const float a0 = e0 * inv, a1 = e1 * inv, a2 = e2 * inv;

    float y0 = a0 * v[base + lane];
    float y1 = a0 * v[base + 32 + lane];
    if (t >= 1) {
        y0 += a1 * v[base - C_EMBD + lane];
        y1 += a1 * v[base - C_EMBD + 32 + lane];
    }
    if (t >= 2) {
        y0 += a2 * v[base - 2 * (size_t)C_EMBD + lane];
        y1 += a2 * v[base - 2 * (size_t)C_EMBD + 32 + lane];
    }
    __nv_bfloat16 h0 = __float2bfloat16(y0);
    __nv_bfloat16 h1 = __float2bfloat16(y1);
    yh[base + lane]      = h0;
    yh[base + 32 + lane] = h1;
    yl[base + lane]      = __float2bfloat16(y0 - __bfloat162float(h0));
    yl[base + 32 + lane] = __float2bfloat16(y1 - __bfloat162float(h1));
}

// ---------------------------------------------------------------------------
extern "C" void kernel_launch(void* const* d_in, const int* in_sizes, int n_in,
                              void* d_out, int out_size)
{
    const float* x  = (const float*)d_in[0];
    const float* W[4]    = {(const float*)d_in[1], (const float*)d_in[3],
                            (const float*)d_in[5], (const float*)d_in[7]};
    const float* bias[4] = {(const float*)d_in[2], (const float*)d_in[4],
                            (const float*)d_in[6], (const float*)d_in[8]};
    float* out = (float*)d_out;

    const int rows = in_sizes[0] / C_EMBD;   // 32768

    __nv_bfloat16 *xh, *xl, *yh, *yl, *wh, *wl;
    float *q, *k, *v;
    cudaGetSymbolAddress((void**)&xh, g_xh);
    cudaGetSymbolAddress((void**)&xl, g_xl);
    cudaGetSymbolAddress((void**)&yh, g_yh);
    cudaGetSymbolAddress((void**)&yl, g_yl);
    cudaGetSymbolAddress((void**)&wh, g_wh);
    cudaGetSymbolAddress((void**)&wl, g_wl);
    cudaGetSymbolAddress((void**)&q, g_q);
    cudaGetSymbolAddress((void**)&k, g_k);
    cudaGetSymbolAddress((void**)&v, g_v);

    cudaFuncSetAttribute(gemm_bf16x3, cudaFuncAttributeMaxDynamicSharedMemorySize,
                         GEMM_SMEM);

    const int xn4 = rows * C_EMBD / 4;
    split_bf16<<<(xn4 + 255) / 256, 256>>>(x, xh, xl, xn4);
    const int wn4 = C_EMBD * C_EMBD / 4;
    for (int i = 0; i < 4; ++i)
        split_bf16<<<(wn4 + 255) / 256, 256>>>(W[i],
            wh + (size_t)i * C_EMBD * C_EMBD, wl + (size_t)i * C_EMBD * C_EMBD, wn4);

    dim3 ggrid(C_EMBD / 128, rows / 128);
    const size_t WSZ = (size_t)C_EMBD * C_EMBD;
    gemm_bf16x3<<<ggrid, 256, GEMM_SMEM>>>(xh, xl, wh + 0 * WSZ, wl + 0 * WSZ, bias[0], q);
    gemm_bf16x3<<<ggrid, 256, GEMM_SMEM>>>(xh, xl, wh + 1 * WSZ, wl + 1 * WSZ, bias[1], k);
    gemm_bf16x3<<<ggrid, 256, GEMM_SMEM>>>(xh, xl, wh + 2 * WSZ, wl + 2 * WSZ, bias[2], v);

    trigram_attn<<<rows, 512>>>(q, k, v, yh, yl);

    gemm_bf16x3<<<ggrid, 256, GEMM_SMEM>>>(yh, yl, wh + 3 * WSZ, wl + 3 * WSZ, bias[3], out);
}

// round 6
// speedup vs baseline: 2.8103x; 1.0657x over previous
#include <cuda_runtime.h>
#include <cuda_bf16.h>
#include <math.h>
#include <stdint.h>

// ---------------------------------------------------------------------------
// TrigramAttention on GB300 (sm_103a), Round 5:
//   mma.sync.m16n8k16.bf16 register GEMM, 3-term split precision:
//     C = Ah*Bh^T + Ah*Bl^T + Al*Bh^T   (fp32 accum, err ~1e-5)
//   R5: CTA tile 256x128 (was 128x128), warp tile 64x64 (was 64x32)
//       -> 2x fragment reuse, SMEM-crossbar pressure per MAC cut ~1.5x.
// ---------------------------------------------------------------------------

#define C_EMBD   1024
#define T_LEN    4096
#define MAX_ROWS (8 * 4096)

#define NCHUNK   16                    // K=1024 / BK=64
#define A_TILE_B 32768                 // 256 rows x 128 bytes
#define B_TILE_B 16384                 // 128 rows x 128 bytes
#define STAGE_B  (2 * A_TILE_B + 2 * B_TILE_B)   // Ah, Al, Bh, Bl = 96KB
#define GEMM_SMEM (2 * STAGE_B)        // 192KB

// ---------------- scratch (__device__ globals: allocation-free rule) --------
__device__ __nv_bfloat16 g_xh[(size_t)MAX_ROWS * C_EMBD];
__device__ __nv_bfloat16 g_xl[(size_t)MAX_ROWS * C_EMBD];
__device__ __nv_bfloat16 g_yh[(size_t)MAX_ROWS * C_EMBD];
__device__ __nv_bfloat16 g_yl[(size_t)MAX_ROWS * C_EMBD];
__device__ __nv_bfloat16 g_wh[4][(size_t)C_EMBD * C_EMBD];
__device__ __nv_bfloat16 g_wl[4][(size_t)C_EMBD * C_EMBD];
__device__ float g_q[(size_t)MAX_ROWS * C_EMBD];
__device__ float g_k[(size_t)MAX_ROWS * C_EMBD];
__device__ float g_v[(size_t)MAX_ROWS * C_EMBD];

// ---------------- helpers ---------------------------------------------------
__device__ __forceinline__ uint32_t smem_u32(const void* p) {
    uint32_t a;
    asm("{ .reg .u64 t; cvta.to.shared.u64 t, %1; cvt.u32.u64 %0, t; }"
        : "=r"(a) : "l"(p));
    return a;
}
__device__ __forceinline__ void cp16(uint32_t dst, const void* src) {
    asm volatile("cp.async.cg.shared.global [%0], [%1], 16;"
                 :: "r"(dst), "l"(src) : "memory");
}
__device__ __forceinline__ uint32_t swz128(uint32_t off) {
    return off ^ ((off >> 3) & 0x70);
}
__device__ __forceinline__ void ldsm4(uint32_t* r, uint32_t addr) {
    asm volatile("ldmatrix.sync.aligned.m8n8.x4.shared.b16 {%0,%1,%2,%3}, [%4];"
                 : "=r"(r[0]), "=r"(r[1]), "=r"(r[2]), "=r"(r[3]) : "r"(addr));
}
__device__ __forceinline__ void mma16816(float* d, const uint32_t* a,
                                         uint32_t b0, uint32_t b1) {
    asm volatile(
        "mma.sync.aligned.m16n8k16.row.col.f32.bf16.bf16.f32 "
        "{%0,%1,%2,%3}, {%4,%5,%6,%7}, {%8,%9}, {%0,%1,%2,%3};"
        : "+f"(d[0]), "+f"(d[1]), "+f"(d[2]), "+f"(d[3])
        : "r"(a[0]), "r"(a[1]), "r"(a[2]), "r"(a[3]), "r"(b0), "r"(b1));
}
// ldmatrix addr inside a (rows x 64 bf16) SW128-swizzled tile.
__device__ __forceinline__ uint32_t ldsm_addr(uint32_t tile, int rowBase,
                                              int kk, int lane) {
    int row   = rowBase + (lane & 15);
    int chunk = kk * 2 + (lane >> 4);
    return tile + (uint32_t)(row * 128 + ((chunk ^ (row & 7)) << 4));
}

// ---------------------------------------------------------------------------
// GEMM: C[m,n] = sum_k Ah[m,k]*Bh[n,k] + Ah*Bl + Al*Bh  + bias[n]
// CTA tile 256x128, BK=64, 8 warps as 4(m)x2(n), warp tile 64x64.
// ---------------------------------------------------------------------------
__global__ __launch_bounds__(256, 1)
void gemm_bf16x3(const __nv_bfloat16* __restrict__ Ah,
                 const __nv_bfloat16* __restrict__ Al,
                 const __nv_bfloat16* __restrict__ Bh,
                 const __nv_bfloat16* __restrict__ Bl,
                 const float* __restrict__ bias,
                 float* __restrict__ Cout)
{
    extern __shared__ char smem[];
    const uint32_t sb = smem_u32(smem);
    const int tid  = threadIdx.x;
    const int wid  = tid >> 5;
    const int lane = tid & 31;
    const int wm   = wid & 3;          // 0..3  (64-row slice of 256)
    const int wn   = wid >> 2;         // 0..1  (64-col slice of 128)
    const int bn   = blockIdx.x * 128;
    const int bm   = blockIdx.y * 256;

    const char* pAh = (const char*)Ah + (size_t)bm * 2048;
    const char* pAl = (const char*)Al + (size_t)bm * 2048;
    const char* pBh = (const char*)Bh + (size_t)bn * 2048;
    const char* pBl = (const char*)Bl + (size_t)bn * 2048;

    float acc[4][8][4];
#pragma unroll
    for (int mt = 0; mt < 4; mt++)
#pragma unroll
        for (int nt = 0; nt < 8; nt++)
#pragma unroll
            for (int r = 0; r < 4; r++) acc[mt][nt][r] = 0.0f;

    // stage loader: Ah/Al 256x64bf16, Bh/Bl 128x64bf16 (96KB total)
    auto load_stage = [&](int chunk, int s) {
        const uint32_t st = sb + s * STAGE_B;
        const size_t kb = (size_t)chunk * 128;
#pragma unroll
        for (int u = 0; u < 8; ++u) {                  // A: 2048 cp16 x2
            const int v   = tid + 256 * u;             // 0..2047
            const int row = v >> 3;                    // 0..255
            const int c16 = v & 7;
            const uint32_t so = swz128((uint32_t)(row * 128 + c16 * 16));
            const size_t go   = (size_t)row * 2048 + kb + c16 * 16;
            cp16(st + so,            pAh + go);
            cp16(st + A_TILE_B + so, pAl + go);
        }
#pragma unroll
        for (int u = 0; u < 4; ++u) {                  // B: 1024 cp16 x2
            const int v   = tid + 256 * u;             // 0..1023
            const int row = v >> 3;                    // 0..127
            const int c16 = v & 7;
            const uint32_t so = swz128((uint32_t)(row * 128 + c16 * 16));
            const size_t go   = (size_t)row * 2048 + kb + c16 * 16;
            cp16(st + 2 * A_TILE_B + so,            pBh + go);
            cp16(st + 2 * A_TILE_B + B_TILE_B + so, pBl + go);
        }
        asm volatile("cp.async.commit_group;" ::: "memory");
    };

    load_stage(0, 0);

    for (int i = 0; i < NCHUNK; ++i) {
        if (i + 1 < NCHUNK) {
            load_stage(i + 1, (i + 1) & 1);
            asm volatile("cp.async.wait_group 1;" ::: "memory");
        } else {
            asm volatile("cp.async.wait_group 0;" ::: "memory");
        }
        __syncthreads();

        const uint32_t st  = sb + (i & 1) * STAGE_B;
        const uint32_t tAh = st;
        const uint32_t tAl = st + A_TILE_B;
        const uint32_t tBh = st + 2 * A_TILE_B;
        const uint32_t tBl = st + 2 * A_TILE_B + B_TILE_B;

#pragma unroll
        for (int kk = 0; kk < 4; ++kk) {
            uint32_t ah[4][4], al[4][4], bh[4][4], bl[4][4];
#pragma unroll
            for (int mt = 0; mt < 4; mt++)
                ldsm4(ah[mt], ldsm_addr(tAh, wm * 64 + mt * 16, kk, lane));
#pragma unroll
            for (int p = 0; p < 4; p++)
                ldsm4(bh[p], ldsm_addr(tBh, wn * 64 + p * 16, kk, lane));
#pragma unroll
            for (int mt = 0; mt < 4; mt++)
#pragma unroll
                for (int nt = 0; nt < 8; nt++)
                    mma16816(acc[mt][nt], ah[mt],
                             bh[nt >> 1][nt & 1], bh[nt >> 1][(nt & 1) + 2]);
#pragma unroll
            for (int p = 0; p < 4; p++)
                ldsm4(bl[p], ldsm_addr(tBl, wn * 64 + p * 16, kk, lane));
#pragma unroll
            for (int mt = 0; mt < 4; mt++)
#pragma unroll
                for (int nt = 0; nt < 8; nt++)
                    mma16816(acc[mt][nt], ah[mt],
                             bl[nt >> 1][nt & 1], bl[nt >> 1][(nt & 1) + 2]);
#pragma unroll
            for (int mt = 0; mt < 4; mt++)
                ldsm4(al[mt], ldsm_addr(tAl, wm * 64 + mt * 16, kk, lane));
#pragma unroll
            for (int mt = 0; mt < 4; mt++)
#pragma unroll
                for (int nt = 0; nt < 8; nt++)
                    mma16816(acc[mt][nt], al[mt],
                             bh[nt >> 1][nt & 1], bh[nt >> 1][(nt & 1) + 2]);
        }
        __syncthreads();
    }

    // epilogue
    const int g = lane >> 2;
    const int t = lane & 3;
#pragma unroll
    for (int nt = 0; nt < 8; nt++) {
        const int col = bn + wn * 64 + nt * 8 + 2 * t;
        const float b0 = bias[col], b1 = bias[col + 1];
#pragma unroll
        for (int mt = 0; mt < 4; mt++) {
            const int row0 = bm + wm * 64 + mt * 16 + g;
            float2 v0 = {acc[mt][nt][0] + b0, acc[mt][nt][1] + b1};
            float2 v1 = {acc[mt][nt][2] + b0, acc[mt][nt][3] + b1};
            *(float2*)(Cout + (size_t)row0 * C_EMBD + col)       = v0;
            *(float2*)(Cout + (size_t)(row0 + 8) * C_EMBD + col) = v1;
        }
    }
}

// ---------------------------------------------------------------------------
__global__ __launch_bounds__(256)
void split_bf16(const float* __restrict__ in, __nv_bfloat16* __restrict__ hi,
                __nv_bfloat16* __restrict__ lo, int n4)
{
    int i = blockIdx.x * 256 + threadIdx.x;
    if (i >= n4) return;
    float4 x = ((const float4*)in)[i];
    __nv_bfloat16 h[4], l[4];
    float v[4] = {x.x, x.y, x.z, x.w};
#pragma unroll
    for (int c = 0; c < 4; ++c) {
        h[c] = __float2bfloat16(v[c]);
        l[c] = __float2bfloat16(v[c] - __bfloat162float(h[c]));
    }
    ((ushort4*)hi)[i] = *(ushort4*)h;
    ((ushort4*)lo)[i] = *(ushort4*)l;
}

// ---------------------------------------------------------------------------
__global__ __launch_bounds__(512)
void trigram_attn(const float* __restrict__ q, const float* __restrict__ k,
                  const float* __restrict__ v,
                  __nv_bfloat16* __restrict__ yh, __nv_bfloat16* __restrict__ yl)
{
    const int row  = blockIdx.x;
    const int t    = row & (T_LEN - 1);
    const int head = threadIdx.x >> 5;
    const int lane = threadIdx.x & 31;
    const size_t base = (size_t)row * C_EMBD + head * 64;

    const float q0 = q[base + lane];
    const float q1 = q[base + 32 + lane];

    float s[3];
#pragma unroll
    for (int j = 0; j < 3; j++) {
        float p = 0.0f;
        if (t >= j) {
            const size_t kb = base - (size_t)j * C_EMBD;
            p = q0 * k[kb + lane] + q1 * k[kb + 32 + lane];
        }
#pragma unroll
        for (int off = 16; off > 0; off >>= 1)
            p += __shfl_xor_sync(0xFFFFFFFFu, p, off);
        s[j] = p * 0.125f;
    }
    float m = s[0];
    if (t >= 1 && s[1] > m) m = s[1];
    if (t >= 2 && s[2] > m) m = s[2];
    float e0 = expf(s[0] - m);
    float e1 = (t >= 1) ? expf(s[1] - m) : 0.0f;
    float e2 = (t >= 2) ? expf(s[2] - m) : 0.0f;
    const float inv = 1.0f / (e0 + e1 + e2);
    const float a0 = e0 * inv, a1 = e1 * inv, a2 = e2 * inv;

    float y0 = a0 * v[base + lane];
    float y1 = a0 * v[base + 32 + lane];
    if (t >= 1) {
        y0 += a1 * v[base - C_EMBD + lane];
        y1 += a1 * v[base - C_EMBD + 32 + lane];
    }
    if (t >= 2) {
        y0 += a2 * v[base - 2 * (size_t)C_EMBD + lane];
        y1 += a2 * v[base - 2 * (size_t)C_EMBD + 32 + lane];
    }
    __nv_bfloat16 h0 = __float2bfloat16(y0);
    __nv_bfloat16 h1 = __float2bfloat16(y1);
    yh[base + lane]      = h0;
    yh[base + 32 + lane] = h1;
    yl[base + lane]      = __float2bfloat16(y0 - __bfloat162float(h0));
    yl[base + 32 + lane] = __float2bfloat16(y1 - __bfloat162float(h1));
}

// ---------------------------------------------------------------------------
extern "C" void kernel_launch(void* const* d_in, const int* in_sizes, int n_in,
                              void* d_out, int out_size)
{
    const float* x  = (const float*)d_in[0];
    const float* W[4]    = {(const float*)d_in[1], (const float*)d_in[3],
                            (const float*)d_in[5], (const float*)d_in[7]};
    const float* bias[4] = {(const float*)d_in[2], (const float*)d_in[4],
                            (const float*)d_in[6], (const float*)d_in[8]};
    float* out = (float*)d_out;

    const int rows = in_sizes[0] / C_EMBD;   // 32768

    __nv_bfloat16 *xh, *xl, *yh, *yl, *wh, *wl;
    float *q, *k, *v;
    cudaGetSymbolAddress((void**)&xh, g_xh);
    cudaGetSymbolAddress((void**)&xl, g_xl);
    cudaGetSymbolAddress((void**)&yh, g_yh);
    cudaGetSymbolAddress((void**)&yl, g_yl);
    cudaGetSymbolAddress((void**)&wh, g_wh);
    cudaGetSymbolAddress((void**)&wl, g_wl);
    cudaGetSymbolAddress((void**)&q, g_q);
    cudaGetSymbolAddress((void**)&k, g_k);
    cudaGetSymbolAddress((void**)&v, g_v);

    cudaFuncSetAttribute(gemm_bf16x3, cudaFuncAttributeMaxDynamicSharedMemorySize,
                         GEMM_SMEM);

    const int xn4 = rows * C_EMBD / 4;
    split_bf16<<<(xn4 + 255) / 256, 256>>>(x, xh, xl, xn4);
    const int wn4 = C_EMBD * C_EMBD / 4;
    for (int i = 0; i < 4; ++i)
        split_bf16<<<(wn4 + 255) / 256, 256>>>(W[i],
            wh + (size_t)i * C_EMBD * C_EMBD, wl + (size_t)i * C_EMBD * C_EMBD, wn4);

    dim3 ggrid(C_EMBD / 128, rows / 256);
    const size_t WSZ = (size_t)C_EMBD * C_EMBD;
    gemm_bf16x3<<<ggrid, 256, GEMM_SMEM>>>(xh, xl, wh + 0 * WSZ, wl + 0 * WSZ, bias[0], q);
    gemm_bf16x3<<<ggrid, 256, GEMM_SMEM>>>(xh, xl, wh + 1 * WSZ, wl + 1 * WSZ, bias[1], k);
    gemm_bf16x3<<<ggrid, 256, GEMM_SMEM>>>(xh, xl, wh + 2 * WSZ, wl + 2 * WSZ, bias[2], v);

    trigram_attn<<<rows, 512>>>(q, k, v, yh, yl);

    gemm_bf16x3<<<ggrid, 256, GEMM_SMEM>>>(yh, yl, wh + 3 * WSZ, wl + 3 * WSZ, bias[3], out);
}

// round 7
// speedup vs baseline: 4.1701x; 1.4838x over previous
#include <cuda_runtime.h>
#include <cuda_fp16.h>
#include <math.h>
#include <stdint.h>

// ---------------------------------------------------------------------------
// TrigramAttention on GB300 (sm_103a), Round 6:
//   fp16 asymmetric split GEMM (2 MMA terms, was bf16 3-term):
//     Ws = 32*W;  Wh = fp16(Ws);  Wl = fp16(Ws - Wh);  A = fp16(x)
//     C = (A*Wh^T + A*Wl^T)/32 + bias         (fp32 accum, err ~2e-4)
//   CTA tile 256x128, BK=64, 8 warps as 4(m)x2(n), warp tile 64x64.
// ---------------------------------------------------------------------------

#define C_EMBD   1024
#define T_LEN    4096
#define MAX_ROWS (8 * 4096)

#define NCHUNK   16                    // K=1024 / BK=64
#define A_TILE_B 32768                 // 256 rows x 128 bytes
#define B_TILE_B 16384                 // 128 rows x 128 bytes
#define STAGE_B  (A_TILE_B + 2 * B_TILE_B)       // A, Wh, Wl = 64KB
#define GEMM_SMEM (2 * STAGE_B)        // 128KB

#define WSCALE     32.0f
#define INV_WSCALE (1.0f / 32.0f)

// ---------------- scratch (__device__ globals: allocation-free rule) --------
__device__ __half g_xh[(size_t)MAX_ROWS * C_EMBD];
__device__ __half g_yh[(size_t)MAX_ROWS * C_EMBD];
__device__ __half g_wh[4][(size_t)C_EMBD * C_EMBD];
__device__ __half g_wl[4][(size_t)C_EMBD * C_EMBD];
__device__ float g_q[(size_t)MAX_ROWS * C_EMBD];
__device__ float g_k[(size_t)MAX_ROWS * C_EMBD];
__device__ float g_v[(size_t)MAX_ROWS * C_EMBD];

// ---------------- helpers ---------------------------------------------------
__device__ __forceinline__ uint32_t smem_u32(const void* p) {
    uint32_t a;
    asm("{ .reg .u64 t; cvta.to.shared.u64 t, %1; cvt.u32.u64 %0, t; }"
        : "=r"(a) : "l"(p));
    return a;
}
__device__ __forceinline__ void cp16(uint32_t dst, const void* src) {
    asm volatile("cp.async.cg.shared.global [%0], [%1], 16;"
                 :: "r"(dst), "l"(src) : "memory");
}
__device__ __forceinline__ uint32_t swz128(uint32_t off) {
    return off ^ ((off >> 3) & 0x70);
}
__device__ __forceinline__ void ldsm4(uint32_t* r, uint32_t addr) {
    asm volatile("ldmatrix.sync.aligned.m8n8.x4.shared.b16 {%0,%1,%2,%3}, [%4];"
                 : "=r"(r[0]), "=r"(r[1]), "=r"(r[2]), "=r"(r[3]) : "r"(addr));
}
__device__ __forceinline__ void mma16816(float* d, const uint32_t* a,
                                         uint32_t b0, uint32_t b1) {
    asm volatile(
        "mma.sync.aligned.m16n8k16.row.col.f32.f16.f16.f32 "
        "{%0,%1,%2,%3}, {%4,%5,%6,%7}, {%8,%9}, {%0,%1,%2,%3};"
        : "+f"(d[0]), "+f"(d[1]), "+f"(d[2]), "+f"(d[3])
        : "r"(a[0]), "r"(a[1]), "r"(a[2]), "r"(a[3]), "r"(b0), "r"(b1));
}
__device__ __forceinline__ uint32_t ldsm_addr(uint32_t tile, int rowBase,
                                              int kk, int lane) {
    int row   = rowBase + (lane & 15);
    int chunk = kk * 2 + (lane >> 4);
    return tile + (uint32_t)(row * 128 + ((chunk ^ (row & 7)) << 4));
}

// ---------------------------------------------------------------------------
// GEMM: C[m,n] = (sum_k A[m,k]*(Wh[n,k]+Wl[n,k])) / 32 + bias[n]
// A:[M,1024] fp16, Wh/Wl:[1024,1024] fp16 (pre-scaled x32).
// ---------------------------------------------------------------------------
__global__ __launch_bounds__(256, 1)
void gemm_fp16x2(const __half* __restrict__ A,
                 const __half* __restrict__ Bh,
                 const __half* __restrict__ Bl,
                 const float* __restrict__ bias,
                 float* __restrict__ Cout)
{
    extern __shared__ char smem[];
    const uint32_t sb = smem_u32(smem);
    const int tid  = threadIdx.x;
    const int wid  = tid >> 5;
    const int lane = tid & 31;
    const int wm   = wid & 3;          // 0..3  (64-row slice of 256)
    const int wn   = wid >> 2;         // 0..1  (64-col slice of 128)
    const int bn   = blockIdx.x * 128;
    const int bm   = blockIdx.y * 256;

    const char* pA  = (const char*)A  + (size_t)bm * 2048;
    const char* pBh = (const char*)Bh + (size_t)bn * 2048;
    const char* pBl = (const char*)Bl + (size_t)bn * 2048;

    float acc[4][8][4];
#pragma unroll
    for (int mt = 0; mt < 4; mt++)
#pragma unroll
        for (int nt = 0; nt < 8; nt++)
#pragma unroll
            for (int r = 0; r < 4; r++) acc[mt][nt][r] = 0.0f;

    auto load_stage = [&](int chunk, int s) {
        const uint32_t st = sb + s * STAGE_B;
        const size_t kb = (size_t)chunk * 128;
#pragma unroll
        for (int u = 0; u < 8; ++u) {                  // A: 2048 cp16
            const int v   = tid + 256 * u;             // 0..2047
            const int row = v >> 3;                    // 0..255
            const int c16 = v & 7;
            const uint32_t so = swz128((uint32_t)(row * 128 + c16 * 16));
            const size_t go   = (size_t)row * 2048 + kb + c16 * 16;
            cp16(st + so, pA + go);
        }
#pragma unroll
        for (int u = 0; u < 4; ++u) {                  // Wh/Wl: 1024 cp16 x2
            const int v   = tid + 256 * u;             // 0..1023
            const int row = v >> 3;                    // 0..127
            const int c16 = v & 7;
            const uint32_t so = swz128((uint32_t)(row * 128 + c16 * 16));
            const size_t go   = (size_t)row * 2048 + kb + c16 * 16;
            cp16(st + A_TILE_B + so,            pBh + go);
            cp16(st + A_TILE_B + B_TILE_B + so, pBl + go);
        }
        asm volatile("cp.async.commit_group;" ::: "memory");
    };

    load_stage(0, 0);

    for (int i = 0; i < NCHUNK; ++i) {
        if (i + 1 < NCHUNK) {
            load_stage(i + 1, (i + 1) & 1);
            asm volatile("cp.async.wait_group 1;" ::: "memory");
        } else {
            asm volatile("cp.async.wait_group 0;" ::: "memory");
        }
        __syncthreads();

        const uint32_t st  = sb + (i & 1) * STAGE_B;
        const uint32_t tA  = st;
        const uint32_t tBh = st + A_TILE_B;
        const uint32_t tBl = st + A_TILE_B + B_TILE_B;

#pragma unroll
        for (int kk = 0; kk < 4; ++kk) {
            uint32_t a[4][4], bh[4][4], bl[4][4];
#pragma unroll
            for (int mt = 0; mt < 4; mt++)
                ldsm4(a[mt], ldsm_addr(tA, wm * 64 + mt * 16, kk, lane));
#pragma unroll
            for (int p = 0; p < 4; p++)
                ldsm4(bh[p], ldsm_addr(tBh, wn * 64 + p * 16, kk, lane));
#pragma unroll
            for (int mt = 0; mt < 4; mt++)
#pragma unroll
                for (int nt = 0; nt < 8; nt++)
                    mma16816(acc[mt][nt], a[mt],
                             bh[nt >> 1][nt & 1], bh[nt >> 1][(nt & 1) + 2]);
#pragma unroll
            for (int p = 0; p < 4; p++)
                ldsm4(bl[p], ldsm_addr(tBl, wn * 64 + p * 16, kk, lane));
#pragma unroll
            for (int mt = 0; mt < 4; mt++)
#pragma unroll
                for (int nt = 0; nt < 8; nt++)
                    mma16816(acc[mt][nt], a[mt],
                             bl[nt >> 1][nt & 1], bl[nt >> 1][(nt & 1) + 2]);
        }
        __syncthreads();
    }

    // epilogue: unscale + bias
    const int g = lane >> 2;
    const int t = lane & 3;
#pragma unroll
    for (int nt = 0; nt < 8; nt++) {
        const int col = bn + wn * 64 + nt * 8 + 2 * t;
        const float b0 = bias[col], b1 = bias[col + 1];
#pragma unroll
        for (int mt = 0; mt < 4; mt++) {
            const int row0 = bm + wm * 64 + mt * 16 + g;
            float2 v0 = {acc[mt][nt][0] * INV_WSCALE + b0,
                         acc[mt][nt][1] * INV_WSCALE + b1};
            float2 v1 = {acc[mt][nt][2] * INV_WSCALE + b0,
                         acc[mt][nt][3] * INV_WSCALE + b1};
            *(float2*)(Cout + (size_t)row0 * C_EMBD + col)       = v0;
            *(float2*)(Cout + (size_t)(row0 + 8) * C_EMBD + col) = v1;
        }
    }
}

// ---------------------------------------------------------------------------
// fp32 -> fp16 convert (activations)
// ---------------------------------------------------------------------------
__global__ __launch_bounds__(256)
void conv_fp16(const float* __restrict__ in, __half* __restrict__ out, int n4)
{
    int i = blockIdx.x * 256 + threadIdx.x;
    if (i >= n4) return;
    float4 x = ((const float4*)in)[i];
    __half h[4] = {__float2half(x.x), __float2half(x.y),
                   __float2half(x.z), __float2half(x.w)};
    ((ushort4*)out)[i] = *(ushort4*)h;
}

// ---------------------------------------------------------------------------
// weight split: Ws = 32*W; Wh = fp16(Ws); Wl = fp16(Ws - Wh)
// ---------------------------------------------------------------------------
__global__ __launch_bounds__(256)
void split_w(const float* __restrict__ in, __half* __restrict__ hi,
             __half* __restrict__ lo, int n4)
{
    int i = blockIdx.x * 256 + threadIdx.x;
    if (i >= n4) return;
    float4 x = ((const float4*)in)[i];
    float v[4] = {x.x * WSCALE, x.y * WSCALE, x.z * WSCALE, x.w * WSCALE};
    __half h[4], l[4];
#pragma unroll
    for (int c = 0; c < 4; ++c) {
        h[c] = __float2half(v[c]);
        l[c] = __float2half(v[c] - __half2float(h[c]));
    }
    ((ushort4*)hi)[i] = *(ushort4*)h;
    ((ushort4*)lo)[i] = *(ushort4*)l;
}

// ---------------------------------------------------------------------------
// Banded trigram attention; emits y as fp16 for the output projection.
// ---------------------------------------------------------------------------
__global__ __launch_bounds__(512)
void trigram_attn(const float* __restrict__ q, const float* __restrict__ k,
                  const float* __restrict__ v, __half* __restrict__ yh)
{
    const int row  = blockIdx.x;
    const int t    = row & (T_LEN - 1);
    const int head = threadIdx.x >> 5;
    const int lane = threadIdx.x & 31;
    const size_t base = (size_t)row * C_EMBD + head * 64;

    const float q0 = q[base + lane];
    const float q1 = q[base + 32 + lane];

    float s[3];
#pragma unroll
    for (int j = 0; j < 3; j++) {
        float p = 0.0f;
        if (t >= j) {
            const size_t kb = base - (size_t)j * C_EMBD;
            p = q0 * k[kb + lane] + q1 * k[kb + 32 + lane];
        }
#pragma unroll
        for (int off = 16; off > 0; off >>= 1)
            p += __shfl_xor_sync(0xFFFFFFFFu, p, off);
        s[j] = p * 0.125f;
    }
    float m = s[0];
    if (t >= 1 && s[1] > m) m = s[1];
    if (t >= 2 && s[2] > m) m = s[2];
    float e0 = expf(s[0] - m);
    float e1 = (t >= 1) ? expf(s[1] - m) : 0.0f;
    float e2 = (t >= 2) ? expf(s[2] - m) : 0.0f;
    const float inv = 1.0f / (e0 + e1 + e2);
    const float a0 = e0 * inv, a1 = e1 * inv, a2 = e2 * inv;

    float y0 = a0 * v[base + lane];
    float y1 = a0 * v[base + 32 + lane];
    if (t >= 1) {
        y0 += a1 * v[base - C_EMBD + lane];
        y1 += a1 * v[base - C_EMBD + 32 + lane];
    }
    if (t >= 2) {
        y0 += a2 * v[base - 2 * (size_t)C_EMBD + lane];
        y1 += a2 * v[base - 2 * (size_t)C_EMBD + 32 + lane];
    }
    yh[base + lane]      = __float2half(y0);
    yh[base + 32 + lane] = __float2half(y1);
}

// ---------------------------------------------------------------------------
extern "C" void kernel_launch(void* const* d_in, const int* in_sizes, int n_in,
                              void* d_out, int out_size)
{
    const float* x  = (const float*)d_in[0];
    const float* W[4]    = {(const float*)d_in[1], (const float*)d_in[3],
                            (const float*)d_in[5], (const float*)d_in[7]};
    const float* bias[4] = {(const float*)d_in[2], (const float*)d_in[4],
                            (const float*)d_in[6], (const float*)d_in[8]};
    float* out = (float*)d_out;

    const int rows = in_sizes[0] / C_EMBD;   // 32768

    __half *xh, *yh, *wh, *wl;
    float *q, *k, *v;
    cudaGetSymbolAddress((void**)&xh, g_xh);
    cudaGetSymbolAddress((void**)&yh, g_yh);
    cudaGetSymbolAddress((void**)&wh, g_wh);
    cudaGetSymbolAddress((void**)&wl, g_wl);
    cudaGetSymbolAddress((void**)&q, g_q);
    cudaGetSymbolAddress((void**)&k, g_k);
    cudaGetSymbolAddress((void**)&v, g_v);

    cudaFuncSetAttribute(gemm_fp16x2, cudaFuncAttributeMaxDynamicSharedMemorySize,
                         GEMM_SMEM);

    const int xn4 = rows * C_EMBD / 4;
    conv_fp16<<<(xn4 + 255) / 256, 256>>>(x, xh, xn4);
    const int wn4 = C_EMBD * C_EMBD / 4;
    for (int i = 0; i < 4; ++i)
        split_w<<<(wn4 + 255) / 256, 256>>>(W[i],
            wh + (size_t)i * C_EMBD * C_EMBD, wl + (size_t)i * C_EMBD * C_EMBD, wn4);

    dim3 ggrid(C_EMBD / 128, rows / 256);
    const size_t WSZ = (size_t)C_EMBD * C_EMBD;
    gemm_fp16x2<<<ggrid, 256, GEMM_SMEM>>>(xh, wh + 0 * WSZ, wl + 0 * WSZ, bias[0], q);
    gemm_fp16x2<<<ggrid, 256, GEMM_SMEM>>>(xh, wh + 1 * WSZ, wl + 1 * WSZ, bias[1], k);
    gemm_fp16x2<<<ggrid, 256, GEMM_SMEM>>>(xh, wh + 2 * WSZ, wl + 2 * WSZ, bias[2], v);

    trigram_attn<<<rows, 512>>>(q, k, v, yh);

    gemm_fp16x2<<<ggrid, 256, GEMM_SMEM>>>(yh, wh + 3 * WSZ, wl + 3 * WSZ, bias[3], out);
}

// round 8
// speedup vs baseline: 6.6389x; 1.5920x over previous
#include <cuda_runtime.h>
#include <cuda_fp16.h>
#include <math.h>
#include <stdint.h>

// ---------------------------------------------------------------------------
// TrigramAttention on GB300 (sm_103a), Round 7:
//   Single-term fp16 GEMM (was 2-term split): C = A*W^T + bias, fp32 accum.
//   Calibrated error budget: ~4.5e-4 total (activations 3.0e-4 measured +
//   fp16 weights ~1.4e-4/GEMM + fp16 q/k/v/y ~1e-4 each, RSS).
//   CTA tile 256x128, BK=64, 8 warps as 4(m)x2(n), warp tile 64x64.
//   GEMM writes fp16 directly for q/k/v/y (templated epilogue).
// ---------------------------------------------------------------------------

#define C_EMBD   1024
#define T_LEN    4096
#define MAX_ROWS (8 * 4096)

#define NCHUNK   16                    // K=1024 / BK=64
#define A_TILE_B 32768                 // 256 rows x 128 bytes
#define B_TILE_B 16384                 // 128 rows x 128 bytes
#define STAGE_B  (A_TILE_B + B_TILE_B)           // A, W = 48KB
#define GEMM_SMEM (2 * STAGE_B)        // 96KB

// ---------------- scratch (__device__ globals: allocation-free rule) --------
__device__ __half g_xh[(size_t)MAX_ROWS * C_EMBD];
__device__ __half g_yh[(size_t)MAX_ROWS * C_EMBD];
__device__ __half g_w[4][(size_t)C_EMBD * C_EMBD];
__device__ __half g_q[(size_t)MAX_ROWS * C_EMBD];
__device__ __half g_k[(size_t)MAX_ROWS * C_EMBD];
__device__ __half g_v[(size_t)MAX_ROWS * C_EMBD];

// ---------------- helpers ---------------------------------------------------
__device__ __forceinline__ uint32_t smem_u32(const void* p) {
    uint32_t a;
    asm("{ .reg .u64 t; cvta.to.shared.u64 t, %1; cvt.u32.u64 %0, t; }"
        : "=r"(a) : "l"(p));
    return a;
}
__device__ __forceinline__ void cp16(uint32_t dst, const void* src) {
    asm volatile("cp.async.cg.shared.global [%0], [%1], 16;"
                 :: "r"(dst), "l"(src) : "memory");
}
__device__ __forceinline__ uint32_t swz128(uint32_t off) {
    return off ^ ((off >> 3) & 0x70);
}
__device__ __forceinline__ void ldsm4(uint32_t* r, uint32_t addr) {
    asm volatile("ldmatrix.sync.aligned.m8n8.x4.shared.b16 {%0,%1,%2,%3}, [%4];"
                 : "=r"(r[0]), "=r"(r[1]), "=r"(r[2]), "=r"(r[3]) : "r"(addr));
}
__device__ __forceinline__ void mma16816(float* d, const uint32_t* a,
                                         uint32_t b0, uint32_t b1) {
    asm volatile(
        "mma.sync.aligned.m16n8k16.row.col.f32.f16.f16.f32 "
        "{%0,%1,%2,%3}, {%4,%5,%6,%7}, {%8,%9}, {%0,%1,%2,%3};"
        : "+f"(d[0]), "+f"(d[1]), "+f"(d[2]), "+f"(d[3])
        : "r"(a[0]), "r"(a[1]), "r"(a[2]), "r"(a[3]), "r"(b0), "r"(b1));
}
__device__ __forceinline__ uint32_t ldsm_addr(uint32_t tile, int rowBase,
                                              int kk, int lane) {
    int row   = rowBase + (lane & 15);
    int chunk = kk * 2 + (lane >> 4);
    return tile + (uint32_t)(row * 128 + ((chunk ^ (row & 7)) << 4));
}
// typed pair-store for the epilogue
__device__ __forceinline__ void store2(float* p, float a, float b) {
    float2 v = {a, b}; *(float2*)p = v;
}
__device__ __forceinline__ void store2(__half* p, float a, float b) {
    *(__half2*)p = __floats2half2_rn(a, b);
}

// ---------------------------------------------------------------------------
// GEMM: C[m,n] = sum_k A[m,k]*W[n,k] + bias[n]
// A:[M,1024] fp16 row-major, W:[1024,1024] fp16 row-major.
// CTA tile 256x128, BK=64, 8 warps as 4(m)x2(n), warp tile 64x64.
// ---------------------------------------------------------------------------
template <typename OutT>
__global__ __launch_bounds__(256, 1)
void gemm_fp16(const __half* __restrict__ A,
               const __half* __restrict__ B,
               const float* __restrict__ bias,
               OutT* __restrict__ Cout)
{
    extern __shared__ char smem[];
    const uint32_t sb = smem_u32(smem);
    const int tid  = threadIdx.x;
    const int wid  = tid >> 5;
    const int lane = tid & 31;
    const int wm   = wid & 3;          // 0..3  (64-row slice of 256)
    const int wn   = wid >> 2;         // 0..1  (64-col slice of 128)
    const int bn   = blockIdx.x * 128;
    const int bm   = blockIdx.y * 256;

    const char* pA = (const char*)A + (size_t)bm * 2048;
    const char* pB = (const char*)B + (size_t)bn * 2048;

    float acc[4][8][4];
#pragma unroll
    for (int mt = 0; mt < 4; mt++)
#pragma unroll
        for (int nt = 0; nt < 8; nt++)
#pragma unroll
            for (int r = 0; r < 4; r++) acc[mt][nt][r] = 0.0f;

    auto load_stage = [&](int chunk, int s) {
        const uint32_t st = sb + s * STAGE_B;
        const size_t kb = (size_t)chunk * 128;
#pragma unroll
        for (int u = 0; u < 8; ++u) {                  // A: 2048 cp16
            const int v   = tid + 256 * u;
            const int row = v >> 3;                    // 0..255
            const int c16 = v & 7;
            const uint32_t so = swz128((uint32_t)(row * 128 + c16 * 16));
            const size_t go   = (size_t)row * 2048 + kb + c16 * 16;
            cp16(st + so, pA + go);
        }
#pragma unroll
        for (int u = 0; u < 4; ++u) {                  // W: 1024 cp16
            const int v   = tid + 256 * u;
            const int row = v >> 3;                    // 0..127
            const int c16 = v & 7;
            const uint32_t so = swz128((uint32_t)(row * 128 + c16 * 16));
            const size_t go   = (size_t)row * 2048 + kb + c16 * 16;
            cp16(st + A_TILE_B + so, pB + go);
        }
        asm volatile("cp.async.commit_group;" ::: "memory");
    };

    load_stage(0, 0);

    for (int i = 0; i < NCHUNK; ++i) {
        if (i + 1 < NCHUNK) {
            load_stage(i + 1, (i + 1) & 1);
            asm volatile("cp.async.wait_group 1;" ::: "memory");
        } else {
            asm volatile("cp.async.wait_group 0;" ::: "memory");
        }
        __syncthreads();

        const uint32_t st = sb + (i & 1) * STAGE_B;
        const uint32_t tA = st;
        const uint32_t tB = st + A_TILE_B;

#pragma unroll
        for (int kk = 0; kk < 4; ++kk) {
            uint32_t a[4][4], b[4][4];
#pragma unroll
            for (int mt = 0; mt < 4; mt++)
                ldsm4(a[mt], ldsm_addr(tA, wm * 64 + mt * 16, kk, lane));
#pragma unroll
            for (int p = 0; p < 4; p++)
                ldsm4(b[p], ldsm_addr(tB, wn * 64 + p * 16, kk, lane));
#pragma unroll
            for (int mt = 0; mt < 4; mt++)
#pragma unroll
                for (int nt = 0; nt < 8; nt++)
                    mma16816(acc[mt][nt], a[mt],
                             b[nt >> 1][nt & 1], b[nt >> 1][(nt & 1) + 2]);
        }
        __syncthreads();
    }

    // epilogue: bias + typed store
    const int g = lane >> 2;
    const int t = lane & 3;
#pragma unroll
    for (int nt = 0; nt < 8; nt++) {
        const int col = bn + wn * 64 + nt * 8 + 2 * t;
        const float b0 = bias[col], b1 = bias[col + 1];
#pragma unroll
        for (int mt = 0; mt < 4; mt++) {
            const int row0 = bm + wm * 64 + mt * 16 + g;
            store2(Cout + (size_t)row0 * C_EMBD + col,
                   acc[mt][nt][0] + b0, acc[mt][nt][1] + b1);
            store2(Cout + (size_t)(row0 + 8) * C_EMBD + col,
                   acc[mt][nt][2] + b0, acc[mt][nt][3] + b1);
        }
    }
}

// ---------------------------------------------------------------------------
// fp32 -> fp16 convert
// ---------------------------------------------------------------------------
__global__ __launch_bounds__(256)
void conv_fp16(const float* __restrict__ in, __half* __restrict__ out, int n4)
{
    int i = blockIdx.x * 256 + threadIdx.x;
    if (i >= n4) return;
    float4 x = ((const float4*)in)[i];
    __half h[4] = {__float2half(x.x), __float2half(x.y),
                   __float2half(x.z), __float2half(x.w)};
    ((ushort4*)out)[i] = *(ushort4*)h;
}

// ---------------------------------------------------------------------------
// Banded trigram attention, fp16 in/out (fp32 math inside).
// warp = one (row, head); lane holds elements 2*lane, 2*lane+1 (half2).
// ---------------------------------------------------------------------------
__global__ __launch_bounds__(512)
void trigram_attn(const __half* __restrict__ q, const __half* __restrict__ k,
                  const __half* __restrict__ v, __half* __restrict__ y)
{
    const int row  = blockIdx.x;
    const int t    = row & (T_LEN - 1);
    const int head = threadIdx.x >> 5;
    const int lane = threadIdx.x & 31;
    const size_t base = (size_t)row * C_EMBD + head * 64;

    const float2 qv = __half22float2(*(const __half2*)(q + base + 2 * lane));

    float s[3];
#pragma unroll
    for (int j = 0; j < 3; j++) {
        float p = 0.0f;
        if (t >= j) {
            const float2 kv = __half22float2(
                *(const __half2*)(k + base - (size_t)j * C_EMBD + 2 * lane));
            p = qv.x * kv.x + qv.y * kv.y;
        }
#pragma unroll
        for (int off = 16; off > 0; off >>= 1)
            p += __shfl_xor_sync(0xFFFFFFFFu, p, off);
        s[j] = p * 0.125f;
    }
    float m = s[0];
    if (t >= 1 && s[1] > m) m = s[1];
    if (t >= 2 && s[2] > m) m = s[2];
    float e0 = expf(s[0] - m);
    float e1 = (t >= 1) ? expf(s[1] - m) : 0.0f;
    float e2 = (t >= 2) ? expf(s[2] - m) : 0.0f;
    const float inv = 1.0f / (e0 + e1 + e2);
    const float a0 = e0 * inv, a1 = e1 * inv, a2 = e2 * inv;

    float2 vv = __half22float2(*(const __half2*)(v + base + 2 * lane));
    float y0 = a0 * vv.x, y1 = a0 * vv.y;
    if (t >= 1) {
        float2 v1f = __half22float2(*(const __half2*)(v + base - C_EMBD + 2 * lane));
        y0 += a1 * v1f.x; y1 += a1 * v1f.y;
    }
    if (t >= 2) {
        float2 v2f = __half22float2(
            *(const __half2*)(v + base - 2 * (size_t)C_EMBD + 2 * lane));
        y0 += a2 * v2f.x; y1 += a2 * v2f.y;
    }
    *(__half2*)(y + base + 2 * lane) = __floats2half2_rn(y0, y1);
}

// ---------------------------------------------------------------------------
extern "C" void kernel_launch(void* const* d_in, const int* in_sizes, int n_in,
                              void* d_out, int out_size)
{
    const float* x  = (const float*)d_in[0];
    const float* W[4]    = {(const float*)d_in[1], (const float*)d_in[3],
                            (const float*)d_in[5], (const float*)d_in[7]};
    const float* bias[4] = {(const float*)d_in[2], (const float*)d_in[4],
                            (const float*)d_in[6], (const float*)d_in[8]};
    float* out = (float*)d_out;

    const int rows = in_sizes[0] / C_EMBD;   // 32768

    __half *xh, *yh, *w, *q, *k, *v;
    cudaGetSymbolAddress((void**)&xh, g_xh);
    cudaGetSymbolAddress((void**)&yh, g_yh);
    cudaGetSymbolAddress((void**)&w,  g_w);
    cudaGetSymbolAddress((void**)&q,  g_q);
    cudaGetSymbolAddress((void**)&k,  g_k);
    cudaGetSymbolAddress((void**)&v,  g_v);

    cudaFuncSetAttribute(gemm_fp16<__half>,
                         cudaFuncAttributeMaxDynamicSharedMemorySize, GEMM_SMEM);
    cudaFuncSetAttribute(gemm_fp16<float>,
                         cudaFuncAttributeMaxDynamicSharedMemorySize, GEMM_SMEM);

    const int xn4 = rows * C_EMBD / 4;
    conv_fp16<<<(xn4 + 255) / 256, 256>>>(x, xh, xn4);
    const int wn4 = C_EMBD * C_EMBD / 4;
    for (int i = 0; i < 4; ++i)
        conv_fp16<<<(wn4 + 255) / 256, 256>>>(W[i],
            w + (size_t)i * C_EMBD * C_EMBD, wn4);

    dim3 ggrid(C_EMBD / 128, rows / 256);
    const size_t WSZ = (size_t)C_EMBD * C_EMBD;
    gemm_fp16<__half><<<ggrid, 256, GEMM_SMEM>>>(xh, w + 0 * WSZ, bias[0], q);
    gemm_fp16<__half><<<ggrid, 256, GEMM_SMEM>>>(xh, w + 1 * WSZ, bias[1], k);
    gemm_fp16<__half><<<ggrid, 256, GEMM_SMEM>>>(xh, w + 2 * WSZ, bias[2], v);

    trigram_attn<<<rows, 512>>>(q, k, v, yh);

    gemm_fp16<float><<<ggrid, 256, GEMM_SMEM>>>(yh, w + 3 * WSZ, bias[3], out);
}